// round 4
// baseline (speedup 1.0000x reference)
#include <cuda_runtime.h>
#include <cuda_bf16.h>
#include <cstdint>

#define VOCAB 500000
#define DIM 128
#define RANK 8
#define SCALING 2.0f
#define RANK_THRESHOLD 0.1f

#define NWARPS 8          // warps per block (256 threads)
#define STAGES 8          // cp.async pipeline depth (tokens in flight per warp)
#define BLOCKS_PER_SM 3   // regs=76 -> 3 resident blocks/SM
#define NSM 148

__device__ int g_idx_is_i64;

__global__ void detect_idx_dtype(const long long* __restrict__ x64, int nsamp) {
    if (threadIdx.x == 0 && blockIdx.x == 0) {
        int ok = 1;
        for (int i = 0; i < nsamp; i++) {
            long long v = x64[i];
            if (v < 0 || v >= (long long)VOCAB) { ok = 0; break; }
        }
        g_idx_is_i64 = ok;
    }
}

__device__ __forceinline__ void cp_async16(uint32_t smem_addr, const void* gptr) {
    asm volatile("cp.async.cg.shared.global [%0], [%1], 16;\n"
                 :: "r"(smem_addr), "l"(gptr));
}
__device__ __forceinline__ void cp_commit() {
    asm volatile("cp.async.commit_group;\n");
}

__global__ void __launch_bounds__(NWARPS * 32)
cora_embed_kernel(const void* __restrict__ xv,
                  const float* __restrict__ E,     // [VOCAB, 128]
                  const float* __restrict__ A,     // [8, 128]
                  const float* __restrict__ Bm,    // [VOCAB, 8]
                  const float* __restrict__ rp,    // [8]
                  float* __restrict__ out,         // [ntok, 128]
                  int ntok, int span)
{
    __shared__ float e_buf[NWARPS][STAGES][DIM];   // 32 KB
    __shared__ float b_buf[NWARPS][STAGES][RANK];  // 2 KB

    const int lane = threadIdx.x & 31;
    const int w    = threadIdx.x >> 5;
    const int warp_global = blockIdx.x * NWARPS + w;

    // Gated+scaled A columns for this lane's 4 output dims.
    float4 a[RANK];
#pragma unroll
    for (int r = 0; r < RANK; r++) {
        float g = (rp[r] > RANK_THRESHOLD) ? SCALING : 0.0f;
        float4 av = reinterpret_cast<const float4*>(A)[r * (DIM / 4) + lane];
        a[r].x = av.x * g; a[r].y = av.y * g; a[r].z = av.z * g; a[r].w = av.w * g;
    }

    const bool is64 = (g_idx_is_i64 != 0);
    const long long* x64 = reinterpret_cast<const long long*>(xv);
    const int*       x32 = reinterpret_cast<const int*>(xv);

    // one contiguous, perfectly balanced span per warp; pipeline never restarts
    const int base = warp_global * span;
    if (base >= ntok) return;
    const int tend = min(base + span, ntok);
    const int nt = tend - base;

    const uint32_t e_base = (uint32_t)__cvta_generic_to_shared(&e_buf[w][0][0]);
    const uint32_t b_base = (uint32_t)__cvta_generic_to_shared(&b_buf[w][0][0]);

    // ---------------- prologue: fill pipeline ----------------
#pragma unroll
    for (int s = 0; s < STAGES; s++) {
        int t = base + s;
        if (t < tend) {
            uint32_t idx = is64 ? (uint32_t)x64[t] : (uint32_t)x32[t];
            cp_async16(e_base + (uint32_t)(s * DIM + lane * 4) * 4,
                       E + (size_t)idx * DIM + lane * 4);
            if (lane < 2)
                cp_async16(b_base + (uint32_t)(s * RANK + lane * 4) * 4,
                           Bm + (size_t)idx * RANK + lane * 4);
        }
        cp_commit();
    }

    // ---------------- steady state ----------------
    for (int i = 0; i < nt; i++) {
        asm volatile("cp.async.wait_group %0;\n" :: "n"(STAGES - 1));
        __syncwarp();   // make lanes 0/1's B copies visible to all lanes

        const int s = i & (STAGES - 1);
        float4 e  = *reinterpret_cast<const float4*>(&e_buf[w][s][lane * 4]);
        float4 b0 = *reinterpret_cast<const float4*>(&b_buf[w][s][0]);
        float4 b1 = *reinterpret_cast<const float4*>(&b_buf[w][s][4]);

        __syncwarp();   // all lanes done reading stage s before refill

        int t = base + i + STAGES;
        if (t < tend) {
            uint32_t idx = is64 ? (uint32_t)x64[t] : (uint32_t)x32[t];
            cp_async16(e_base + (uint32_t)(s * DIM + lane * 4) * 4,
                       E + (size_t)idx * DIM + lane * 4);
            if (lane < 2)
                cp_async16(b_base + (uint32_t)(s * RANK + lane * 4) * 4,
                           Bm + (size_t)idx * RANK + lane * 4);
        }
        cp_commit();

        float4 o = e;
        o.x = fmaf(b0.x, a[0].x, o.x); o.y = fmaf(b0.x, a[0].y, o.y);
        o.z = fmaf(b0.x, a[0].z, o.z); o.w = fmaf(b0.x, a[0].w, o.w);
        o.x = fmaf(b0.y, a[1].x, o.x); o.y = fmaf(b0.y, a[1].y, o.y);
        o.z = fmaf(b0.y, a[1].z, o.z); o.w = fmaf(b0.y, a[1].w, o.w);
        o.x = fmaf(b0.z, a[2].x, o.x); o.y = fmaf(b0.z, a[2].y, o.y);
        o.z = fmaf(b0.z, a[2].z, o.z); o.w = fmaf(b0.z, a[2].w, o.w);
        o.x = fmaf(b0.w, a[3].x, o.x); o.y = fmaf(b0.w, a[3].y, o.y);
        o.z = fmaf(b0.w, a[3].z, o.z); o.w = fmaf(b0.w, a[3].w, o.w);
        o.x = fmaf(b1.x, a[4].x, o.x); o.y = fmaf(b1.x, a[4].y, o.y);
        o.z = fmaf(b1.x, a[4].z, o.z); o.w = fmaf(b1.x, a[4].w, o.w);
        o.x = fmaf(b1.y, a[5].x, o.x); o.y = fmaf(b1.y, a[5].y, o.y);
        o.z = fmaf(b1.y, a[5].z, o.z); o.w = fmaf(b1.y, a[5].w, o.w);
        o.x = fmaf(b1.z, a[6].x, o.x); o.y = fmaf(b1.z, a[6].y, o.y);
        o.z = fmaf(b1.z, a[6].z, o.z); o.w = fmaf(b1.z, a[6].w, o.w);
        o.x = fmaf(b1.w, a[7].x, o.x); o.y = fmaf(b1.w, a[7].y, o.y);
        o.z = fmaf(b1.w, a[7].z, o.z); o.w = fmaf(b1.w, a[7].w, o.w);

        __stcs(reinterpret_cast<float4*>(out + (size_t)(base + i) * DIM) + lane, o);
    }
}

extern "C" void kernel_launch(void* const* d_in, const int* in_sizes, int n_in,
                              void* d_out, int out_size)
{
    const void*  x  = d_in[0];                // [B, L] int32 or int64
    const float* E  = (const float*)d_in[1];  // [VOCAB, 128]
    const float* A  = (const float*)d_in[2];  // [8, 128]
    const float* Bm = (const float*)d_in[3];  // [VOCAB, 8]
    const float* rp = (const float*)d_in[4];  // [8]
    float* out = (float*)d_out;

    const int ntok = out_size / DIM;

    detect_idx_dtype<<<1, 32>>>((const long long*)x, 64);

    // persistent, perfectly balanced: one wave of 3 blocks/SM
    int blocks = NSM * BLOCKS_PER_SM;                       // 444
    int total_warps = blocks * NWARPS;                      // 3552
    int span = (ntok + total_warps - 1) / total_warps;      // ~231 contiguous tokens/warp
    // don't launch more blocks than needed for tiny inputs
    int needed_blocks = (ntok + NWARPS * span - 1) / (NWARPS * span);
    if (needed_blocks < blocks) blocks = needed_blocks;

    cora_embed_kernel<<<blocks, NWARPS * 32>>>(x, E, A, Bm, rp, out, ntok, span);
}

// round 5
// speedup vs baseline: 1.0602x; 1.0602x over previous
#include <cuda_runtime.h>
#include <cuda_bf16.h>
#include <cstdint>

#define VOCAB 500000
#define DIM 128
#define RANK 8
#define SCALING 2.0f
#define RANK_THRESHOLD 0.1f

#define NWARPS 8          // warps per block (256 threads)
#define STAGES 8          // cp.async pipeline depth (tokens in flight per warp)
#define CHUNK 64          // tokens per warp chunk (small chunks + multi-wave self-balancing)

__device__ int g_idx_is_i64;

__global__ void detect_idx_dtype(const long long* __restrict__ x64, int nsamp) {
    if (threadIdx.x == 0 && blockIdx.x == 0) {
        int ok = 1;
        for (int i = 0; i < nsamp; i++) {
            long long v = x64[i];
            if (v < 0 || v >= (long long)VOCAB) { ok = 0; break; }
        }
        g_idx_is_i64 = ok;
    }
}

__device__ __forceinline__ void cp_async16(uint32_t smem_addr, const void* gptr) {
    asm volatile("cp.async.cg.shared.global [%0], [%1], 16;\n"
                 :: "r"(smem_addr), "l"(gptr));
}
__device__ __forceinline__ void cp_commit() {
    asm volatile("cp.async.commit_group;\n");
}

__global__ void __launch_bounds__(NWARPS * 32, 4)   // force regs<=64 -> 4 blocks/SM
cora_embed_kernel(const void* __restrict__ xv,
                  const float* __restrict__ E,     // [VOCAB, 128]
                  const float* __restrict__ A,     // [8, 128]
                  const float* __restrict__ Bm,    // [VOCAB, 8]
                  const float* __restrict__ rp,    // [8]
                  float* __restrict__ out,         // [ntok, 128]
                  int ntok)
{
    __shared__ float e_buf[NWARPS][STAGES][DIM];   // 32 KB
    __shared__ float b_buf[NWARPS][STAGES][RANK];  // 2 KB

    const int lane = threadIdx.x & 31;
    const int w    = threadIdx.x >> 5;
    const int warp_global = blockIdx.x * NWARPS + w;

    // Gated+scaled A columns for this lane's 4 output dims (32 regs, reused all tokens).
    float4 a[RANK];
#pragma unroll
    for (int r = 0; r < RANK; r++) {
        float g = (rp[r] > RANK_THRESHOLD) ? SCALING : 0.0f;
        float4 av = reinterpret_cast<const float4*>(A)[r * (DIM / 4) + lane];
        a[r].x = av.x * g; a[r].y = av.y * g; a[r].z = av.z * g; a[r].w = av.w * g;
    }

    const bool is64 = (g_idx_is_i64 != 0);
    const long long* x64 = reinterpret_cast<const long long*>(xv);
    const int*       x32 = reinterpret_cast<const int*>(xv);

    const int base = warp_global * CHUNK;
    if (base >= ntok) return;
    const int tend = min(base + CHUNK, ntok);
    const int nt = tend - base;

    const uint32_t e_base = (uint32_t)__cvta_generic_to_shared(&e_buf[w][0][0]);
    const uint32_t b_base = (uint32_t)__cvta_generic_to_shared(&b_buf[w][0][0]);

    // ---------------- prologue: fill pipeline ----------------
#pragma unroll
    for (int s = 0; s < STAGES; s++) {
        int t = base + s;
        if (t < tend) {
            uint32_t idx = is64 ? (uint32_t)x64[t] : (uint32_t)x32[t];
            cp_async16(e_base + (uint32_t)(s * DIM + lane * 4) * 4,
                       E + (size_t)idx * DIM + lane * 4);
            if (lane < 2)
                cp_async16(b_base + (uint32_t)(s * RANK + lane * 4) * 4,
                           Bm + (size_t)idx * RANK + lane * 4);
        }
        cp_commit();
    }

    // ---------------- steady state ----------------
    for (int i = 0; i < nt; i++) {
        asm volatile("cp.async.wait_group %0;\n" :: "n"(STAGES - 1));
        __syncwarp();   // make lanes 0/1's B copies visible to all lanes

        const int s = i & (STAGES - 1);
        float4 e  = *reinterpret_cast<const float4*>(&e_buf[w][s][lane * 4]);
        float4 b0 = *reinterpret_cast<const float4*>(&b_buf[w][s][0]);
        float4 b1 = *reinterpret_cast<const float4*>(&b_buf[w][s][4]);

        __syncwarp();   // all lanes done reading stage s before refill

        int t = base + i + STAGES;
        if (t < tend) {
            uint32_t idx = is64 ? (uint32_t)x64[t] : (uint32_t)x32[t];
            cp_async16(e_base + (uint32_t)(s * DIM + lane * 4) * 4,
                       E + (size_t)idx * DIM + lane * 4);
            if (lane < 2)
                cp_async16(b_base + (uint32_t)(s * RANK + lane * 4) * 4,
                           Bm + (size_t)idx * RANK + lane * 4);
        }
        cp_commit();

        float4 o = e;
        o.x = fmaf(b0.x, a[0].x, o.x); o.y = fmaf(b0.x, a[0].y, o.y);
        o.z = fmaf(b0.x, a[0].z, o.z); o.w = fmaf(b0.x, a[0].w, o.w);
        o.x = fmaf(b0.y, a[1].x, o.x); o.y = fmaf(b0.y, a[1].y, o.y);
        o.z = fmaf(b0.y, a[1].z, o.z); o.w = fmaf(b0.y, a[1].w, o.w);
        o.x = fmaf(b0.z, a[2].x, o.x); o.y = fmaf(b0.z, a[2].y, o.y);
        o.z = fmaf(b0.z, a[2].z, o.z); o.w = fmaf(b0.z, a[2].w, o.w);
        o.x = fmaf(b0.w, a[3].x, o.x); o.y = fmaf(b0.w, a[3].y, o.y);
        o.z = fmaf(b0.w, a[3].z, o.z); o.w = fmaf(b0.w, a[3].w, o.w);
        o.x = fmaf(b1.x, a[4].x, o.x); o.y = fmaf(b1.x, a[4].y, o.y);
        o.z = fmaf(b1.x, a[4].z, o.z); o.w = fmaf(b1.x, a[4].w, o.w);
        o.x = fmaf(b1.y, a[5].x, o.x); o.y = fmaf(b1.y, a[5].y, o.y);
        o.z = fmaf(b1.y, a[5].z, o.z); o.w = fmaf(b1.y, a[5].w, o.w);
        o.x = fmaf(b1.z, a[6].x, o.x); o.y = fmaf(b1.z, a[6].y, o.y);
        o.z = fmaf(b1.z, a[6].z, o.z); o.w = fmaf(b1.z, a[6].w, o.w);
        o.x = fmaf(b1.w, a[7].x, o.x); o.y = fmaf(b1.w, a[7].y, o.y);
        o.z = fmaf(b1.w, a[7].z, o.z); o.w = fmaf(b1.w, a[7].w, o.w);

        __stcs(reinterpret_cast<float4*>(out + (size_t)(base + i) * DIM) + lane, o);
    }
}

extern "C" void kernel_launch(void* const* d_in, const int* in_sizes, int n_in,
                              void* d_out, int out_size)
{
    const void*  x  = d_in[0];                // [B, L] int32 or int64
    const float* E  = (const float*)d_in[1];  // [VOCAB, 128]
    const float* A  = (const float*)d_in[2];  // [8, 128]
    const float* Bm = (const float*)d_in[3];  // [VOCAB, 8]
    const float* rp = (const float*)d_in[4];  // [8]
    float* out = (float*)d_out;

    const int ntok = out_size / DIM;

    detect_idx_dtype<<<1, 32>>>((const long long*)x, 64);

    const int tok_per_block = NWARPS * CHUNK;               // 512
    int blocks = (ntok + tok_per_block - 1) / tok_per_block; // 1600 for 819200 tokens
    cora_embed_kernel<<<blocks, NWARPS * 32>>>(x, E, A, Bm, rp, out, ntok);
}

// round 6
// speedup vs baseline: 1.1150x; 1.0516x over previous
#include <cuda_runtime.h>
#include <cuda_bf16.h>
#include <cstdint>

#define VOCAB 500000
#define DIM 128
#define RANK 8
#define SCALING 2.0f
#define RANK_THRESHOLD 0.1f

#define NWARPS 8          // warps per block (256 threads)
#define STAGES 8          // cp.async pipeline depth (tokens in flight per warp)
#define CHUNK 64          // tokens per warp chunk (small chunks + multi-wave balancing)

__device__ int g_idx_is_i64;

__global__ void detect_idx_dtype(const long long* __restrict__ x64, int nsamp) {
    if (threadIdx.x == 0 && blockIdx.x == 0) {
        int ok = 1;
        for (int i = 0; i < nsamp; i++) {
            long long v = x64[i];
            if (v < 0 || v >= (long long)VOCAB) { ok = 0; break; }
        }
        g_idx_is_i64 = ok;
    }
}

__device__ __forceinline__ void cp_async16(uint32_t smem_addr, const void* gptr) {
    asm volatile("cp.async.cg.shared.global [%0], [%1], 16;\n"
                 :: "r"(smem_addr), "l"(gptr));
}
__device__ __forceinline__ void cp_commit() {
    asm volatile("cp.async.commit_group;\n");
}

// ---- packed f32x2 helpers (FFMA2 is only reachable via PTX fma.rn.f32x2) ----
__device__ __forceinline__ uint64_t pack2(float lo, float hi) {
    uint64_t r; asm("mov.b64 %0, {%1, %2};" : "=l"(r) : "f"(lo), "f"(hi)); return r;
}
__device__ __forceinline__ uint64_t bcast2(float v) {
    uint64_t r; asm("mov.b64 %0, {%1, %1};" : "=l"(r) : "f"(v)); return r;
}
__device__ __forceinline__ uint64_t fma2(uint64_t a, uint64_t b, uint64_t c) {
    uint64_t d; asm("fma.rn.f32x2 %0, %1, %2, %3;" : "=l"(d) : "l"(a), "l"(b), "l"(c)); return d;
}
__device__ __forceinline__ void unpack2(uint64_t v, float& lo, float& hi) {
    asm("mov.b64 {%0, %1}, %2;" : "=f"(lo), "=f"(hi) : "l"(v));
}

__global__ void __launch_bounds__(NWARPS * 32)
cora_embed_kernel(const void* __restrict__ xv,
                  const float* __restrict__ E,     // [VOCAB, 128]
                  const float* __restrict__ A,     // [8, 128]
                  const float* __restrict__ Bm,    // [VOCAB, 8]
                  const float* __restrict__ rp,    // [8]
                  float* __restrict__ out,         // [ntok, 128]
                  int ntok)
{
    __shared__ float e_buf[NWARPS][STAGES][DIM];   // 32 KB
    __shared__ float b_buf[NWARPS][STAGES][RANK];  // 2 KB

    const int lane = threadIdx.x & 31;
    const int w    = threadIdx.x >> 5;
    const int warp_global = blockIdx.x * NWARPS + w;

    // Gated+scaled A columns for this lane's 4 dims, packed as f32x2 pairs.
    uint64_t a2[RANK][2];
#pragma unroll
    for (int r = 0; r < RANK; r++) {
        float g = (rp[r] > RANK_THRESHOLD) ? SCALING : 0.0f;
        float4 av = reinterpret_cast<const float4*>(A)[r * (DIM / 4) + lane];
        a2[r][0] = pack2(av.x * g, av.y * g);
        a2[r][1] = pack2(av.z * g, av.w * g);
    }

    const bool is64 = (g_idx_is_i64 != 0);
    const long long* x64 = reinterpret_cast<const long long*>(xv);
    const int*       x32 = reinterpret_cast<const int*>(xv);

    const int base = warp_global * CHUNK;
    if (base >= ntok) return;
    const int tend = min(base + CHUNK, ntok);
    const int nt = tend - base;

    const uint32_t e_base = (uint32_t)__cvta_generic_to_shared(&e_buf[w][0][0]);
    const uint32_t b_base = (uint32_t)__cvta_generic_to_shared(&b_buf[w][0][0]);

    // ---------------- prologue: fill pipeline ----------------
#pragma unroll
    for (int s = 0; s < STAGES; s++) {
        int t = base + s;
        if (t < tend) {
            uint32_t idx = is64 ? (uint32_t)x64[t] : (uint32_t)x32[t];
            cp_async16(e_base + (uint32_t)(s * DIM + lane * 4) * 4,
                       E + (size_t)idx * DIM + lane * 4);
            if (lane < 2)
                cp_async16(b_base + (uint32_t)(s * RANK + lane * 4) * 4,
                           Bm + (size_t)idx * RANK + lane * 4);
        }
        cp_commit();
    }

    // ---------------- steady state ----------------
    for (int i = 0; i < nt; i++) {
        asm volatile("cp.async.wait_group %0;\n" :: "n"(STAGES - 1));
        __syncwarp();   // make lanes 0/1's B copies visible to all lanes

        const int s = i & (STAGES - 1);
        float4 e  = *reinterpret_cast<const float4*>(&e_buf[w][s][lane * 4]);
        float4 b0 = *reinterpret_cast<const float4*>(&b_buf[w][s][0]);
        float4 b1 = *reinterpret_cast<const float4*>(&b_buf[w][s][4]);

        __syncwarp();   // all lanes done reading stage s before refill

        int t = base + i + STAGES;
        if (t < tend) {
            uint32_t idx = is64 ? (uint32_t)x64[t] : (uint32_t)x32[t];
            cp_async16(e_base + (uint32_t)(s * DIM + lane * 4) * 4,
                       E + (size_t)idx * DIM + lane * 4);
            if (lane < 2)
                cp_async16(b_base + (uint32_t)(s * RANK + lane * 4) * 4,
                           Bm + (size_t)idx * RANK + lane * 4);
        }
        cp_commit();

        // packed f32x2 math: 16 FFMA2 + 8 broadcasts instead of 32 FFMA
        uint64_t o0 = pack2(e.x, e.y);
        uint64_t o1 = pack2(e.z, e.w);
        uint64_t bb;
        bb = bcast2(b0.x); o0 = fma2(bb, a2[0][0], o0); o1 = fma2(bb, a2[0][1], o1);
        bb = bcast2(b0.y); o0 = fma2(bb, a2[1][0], o0); o1 = fma2(bb, a2[1][1], o1);
        bb = bcast2(b0.z); o0 = fma2(bb, a2[2][0], o0); o1 = fma2(bb, a2[2][1], o1);
        bb = bcast2(b0.w); o0 = fma2(bb, a2[3][0], o0); o1 = fma2(bb, a2[3][1], o1);
        bb = bcast2(b1.x); o0 = fma2(bb, a2[4][0], o0); o1 = fma2(bb, a2[4][1], o1);
        bb = bcast2(b1.y); o0 = fma2(bb, a2[5][0], o0); o1 = fma2(bb, a2[5][1], o1);
        bb = bcast2(b1.z); o0 = fma2(bb, a2[6][0], o0); o1 = fma2(bb, a2[6][1], o1);
        bb = bcast2(b1.w); o0 = fma2(bb, a2[7][0], o0); o1 = fma2(bb, a2[7][1], o1);

        float4 o;
        unpack2(o0, o.x, o.y);
        unpack2(o1, o.z, o.w);

        __stcs(reinterpret_cast<float4*>(out + (size_t)(base + i) * DIM) + lane, o);
    }
}

extern "C" void kernel_launch(void* const* d_in, const int* in_sizes, int n_in,
                              void* d_out, int out_size)
{
    const void*  x  = d_in[0];                // [B, L] int32 or int64
    const float* E  = (const float*)d_in[1];  // [VOCAB, 128]
    const float* A  = (const float*)d_in[2];  // [8, 128]
    const float* Bm = (const float*)d_in[3];  // [VOCAB, 8]
    const float* rp = (const float*)d_in[4];  // [8]
    float* out = (float*)d_out;

    const int ntok = out_size / DIM;

    detect_idx_dtype<<<1, 32>>>((const long long*)x, 64);

    const int tok_per_block = NWARPS * CHUNK;                // 512
    int blocks = (ntok + tok_per_block - 1) / tok_per_block; // 1600
    cora_embed_kernel<<<blocks, NWARPS * 32>>>(x, E, A, Bm, rp, out, ntok);
}

// round 7
// speedup vs baseline: 1.1379x; 1.0206x over previous
#include <cuda_runtime.h>
#include <cuda_bf16.h>
#include <cstdint>

#define VOCAB 500000
#define DIM 128
#define RANK 8
#define SCALING 2.0f
#define RANK_THRESHOLD 0.1f

#define NWARPS 8          // warps per block (256 threads)
#define STAGES 8          // cp.async pipeline depth (tokens in flight per warp)
#define CHUNK 64          // tokens per warp chunk (small chunks + multi-wave balancing)

__device__ __forceinline__ void cp_async16(uint32_t smem_addr, const void* gptr) {
    asm volatile("cp.async.cg.shared.global [%0], [%1], 16;\n"
                 :: "r"(smem_addr), "l"(gptr));
}
__device__ __forceinline__ void cp_commit() {
    asm volatile("cp.async.commit_group;\n");
}

// ---- packed f32x2 helpers (FFMA2 is only reachable via PTX fma.rn.f32x2) ----
__device__ __forceinline__ uint64_t pack2(float lo, float hi) {
    uint64_t r; asm("mov.b64 %0, {%1, %2};" : "=l"(r) : "f"(lo), "f"(hi)); return r;
}
__device__ __forceinline__ uint64_t bcast2(float v) {
    uint64_t r; asm("mov.b64 %0, {%1, %1};" : "=l"(r) : "f"(v)); return r;
}
__device__ __forceinline__ uint64_t fma2(uint64_t a, uint64_t b, uint64_t c) {
    uint64_t d; asm("fma.rn.f32x2 %0, %1, %2, %3;" : "=l"(d) : "l"(a), "l"(b), "l"(c)); return d;
}
__device__ __forceinline__ void unpack2(uint64_t v, float& lo, float& hi) {
    asm("mov.b64 {%0, %1}, %2;" : "=f"(lo), "=f"(hi) : "l"(v));
}

__global__ void __launch_bounds__(NWARPS * 32)
cora_embed_kernel(const void* __restrict__ xv,
                  const float* __restrict__ E,     // [VOCAB, 128]
                  const float* __restrict__ A,     // [8, 128]
                  const float* __restrict__ Bm,    // [VOCAB, 8]
                  const float* __restrict__ rp,    // [8]
                  float* __restrict__ out,         // [ntok, 128]
                  int ntok)
{
    __shared__ float e_buf[NWARPS][STAGES][DIM];   // 32 KB
    __shared__ float b_buf[NWARPS][STAGES][RANK];  // 2 KB

    const int lane = threadIdx.x & 31;
    const int w    = threadIdx.x >> 5;
    const int warp_global = blockIdx.x * NWARPS + w;

    // ---- inline index-dtype detection (replaces separate detector kernel) ----
    // All warps read the same first 32 int64 slots (one L2 line set, broadcast).
    // If data is int32, an int64 view is >= 2^32 unless the paired odd word is 0
    // (P ~ (1/VOCAB)^32 across 32 samples ~= 0).
    const long long* x64 = reinterpret_cast<const long long*>(xv);
    const int*       x32 = reinterpret_cast<const int*>(xv);
    long long probe = x64[lane];
    bool bad = (probe < 0) || (probe >= (long long)VOCAB);
    const bool is64 = (__ballot_sync(0xFFFFFFFFu, bad) == 0u);

    // Gated+scaled A columns for this lane's 4 dims, packed as f32x2 pairs.
    uint64_t a2[RANK][2];
#pragma unroll
    for (int r = 0; r < RANK; r++) {
        float g = (rp[r] > RANK_THRESHOLD) ? SCALING : 0.0f;
        float4 av = reinterpret_cast<const float4*>(A)[r * (DIM / 4) + lane];
        a2[r][0] = pack2(av.x * g, av.y * g);
        a2[r][1] = pack2(av.z * g, av.w * g);
    }

    const int base = warp_global * CHUNK;
    if (base >= ntok) return;
    const int tend = min(base + CHUNK, ntok);
    const int nt = tend - base;

    const uint32_t e_base = (uint32_t)__cvta_generic_to_shared(&e_buf[w][0][0]);
    const uint32_t b_base = (uint32_t)__cvta_generic_to_shared(&b_buf[w][0][0]);

    // ---------------- prologue: fill pipeline ----------------
#pragma unroll
    for (int s = 0; s < STAGES; s++) {
        int t = base + s;
        if (t < tend) {
            uint32_t idx = is64 ? (uint32_t)x64[t] : (uint32_t)x32[t];
            cp_async16(e_base + (uint32_t)(s * DIM + lane * 4) * 4,
                       E + (size_t)idx * DIM + lane * 4);
            if (lane < 2)
                cp_async16(b_base + (uint32_t)(s * RANK + lane * 4) * 4,
                           Bm + (size_t)idx * RANK + lane * 4);
        }
        cp_commit();
    }

    // ---------------- steady state ----------------
    for (int i = 0; i < nt; i++) {
        asm volatile("cp.async.wait_group %0;\n" :: "n"(STAGES - 1));
        __syncwarp();   // make lanes 0/1's B copies visible to all lanes

        const int s = i & (STAGES - 1);
        float4 e  = *reinterpret_cast<const float4*>(&e_buf[w][s][lane * 4]);
        float4 b0 = *reinterpret_cast<const float4*>(&b_buf[w][s][0]);
        float4 b1 = *reinterpret_cast<const float4*>(&b_buf[w][s][4]);

        __syncwarp();   // all lanes done reading stage s before refill

        int t = base + i + STAGES;
        if (t < tend) {
            uint32_t idx = is64 ? (uint32_t)x64[t] : (uint32_t)x32[t];
            cp_async16(e_base + (uint32_t)(s * DIM + lane * 4) * 4,
                       E + (size_t)idx * DIM + lane * 4);
            if (lane < 2)
                cp_async16(b_base + (uint32_t)(s * RANK + lane * 4) * 4,
                           Bm + (size_t)idx * RANK + lane * 4);
        }
        cp_commit();

        // packed f32x2 math: 16 FFMA2 + 8 broadcasts instead of 32 FFMA
        uint64_t o0 = pack2(e.x, e.y);
        uint64_t o1 = pack2(e.z, e.w);
        uint64_t bb;
        bb = bcast2(b0.x); o0 = fma2(bb, a2[0][0], o0); o1 = fma2(bb, a2[0][1], o1);
        bb = bcast2(b0.y); o0 = fma2(bb, a2[1][0], o0); o1 = fma2(bb, a2[1][1], o1);
        bb = bcast2(b0.z); o0 = fma2(bb, a2[2][0], o0); o1 = fma2(bb, a2[2][1], o1);
        bb = bcast2(b0.w); o0 = fma2(bb, a2[3][0], o0); o1 = fma2(bb, a2[3][1], o1);
        bb = bcast2(b1.x); o0 = fma2(bb, a2[4][0], o0); o1 = fma2(bb, a2[4][1], o1);
        bb = bcast2(b1.y); o0 = fma2(bb, a2[5][0], o0); o1 = fma2(bb, a2[5][1], o1);
        bb = bcast2(b1.z); o0 = fma2(bb, a2[6][0], o0); o1 = fma2(bb, a2[6][1], o1);
        bb = bcast2(b1.w); o0 = fma2(bb, a2[7][0], o0); o1 = fma2(bb, a2[7][1], o1);

        float4 o;
        unpack2(o0, o.x, o.y);
        unpack2(o1, o.z, o.w);

        __stcs(reinterpret_cast<float4*>(out + (size_t)(base + i) * DIM) + lane, o);
    }
}

extern "C" void kernel_launch(void* const* d_in, const int* in_sizes, int n_in,
                              void* d_out, int out_size)
{
    const void*  x  = d_in[0];                // [B, L] int32 or int64
    const float* E  = (const float*)d_in[1];  // [VOCAB, 128]
    const float* A  = (const float*)d_in[2];  // [8, 128]
    const float* Bm = (const float*)d_in[3];  // [VOCAB, 8]
    const float* rp = (const float*)d_in[4];  // [8]
    float* out = (float*)d_out;

    const int ntok = out_size / DIM;

    const int tok_per_block = NWARPS * CHUNK;                // 512
    int blocks = (ntok + tok_per_block - 1) / tok_per_block; // 1600
    cora_embed_kernel<<<blocks, NWARPS * 32>>>(x, E, A, Bm, rp, out, ntok);
}

// round 8
// speedup vs baseline: 1.1382x; 1.0002x over previous
#include <cuda_runtime.h>
#include <cuda_bf16.h>
#include <cstdint>

#define VOCAB 500000
#define DIM 128
#define RANK 8
#define SCALING 2.0f
#define RANK_THRESHOLD 0.1f

#define NWARPS 8          // warps per block (256 threads)
#define STAGES 8          // cp.async pipeline depth (tokens in flight per warp)
#define CHUNK 64          // tokens per warp chunk (small chunks + multi-wave balancing)

// cp.async 16B with L2 evict_last cache hint (protect gathered rows from the
// streaming write traffic in L2).
__device__ __forceinline__ void cp_async16_el(uint32_t smem_addr, const void* gptr,
                                              uint64_t pol) {
    asm volatile("cp.async.cg.shared.global.L2::cache_hint [%0], [%1], 16, %2;\n"
                 :: "r"(smem_addr), "l"(gptr), "l"(pol));
}
__device__ __forceinline__ void cp_commit() {
    asm volatile("cp.async.commit_group;\n");
}
__device__ __forceinline__ uint64_t mk_evict_last_policy() {
    uint64_t pol;
    asm("createpolicy.fractional.L2::evict_last.b64 %0, 1.0;" : "=l"(pol));
    return pol;
}

// ---- packed f32x2 helpers (FFMA2 is only reachable via PTX fma.rn.f32x2) ----
__device__ __forceinline__ uint64_t pack2(float lo, float hi) {
    uint64_t r; asm("mov.b64 %0, {%1, %2};" : "=l"(r) : "f"(lo), "f"(hi)); return r;
}
__device__ __forceinline__ uint64_t bcast2(float v) {
    uint64_t r; asm("mov.b64 %0, {%1, %1};" : "=l"(r) : "f"(v)); return r;
}
__device__ __forceinline__ uint64_t fma2(uint64_t a, uint64_t b, uint64_t c) {
    uint64_t d; asm("fma.rn.f32x2 %0, %1, %2, %3;" : "=l"(d) : "l"(a), "l"(b), "l"(c)); return d;
}
__device__ __forceinline__ void unpack2(uint64_t v, float& lo, float& hi) {
    asm("mov.b64 {%0, %1}, %2;" : "=f"(lo), "=f"(hi) : "l"(v));
}

__global__ void __launch_bounds__(NWARPS * 32)
cora_embed_kernel(const void* __restrict__ xv,
                  const float* __restrict__ E,     // [VOCAB, 128]
                  const float* __restrict__ A,     // [8, 128]
                  const float* __restrict__ Bm,    // [VOCAB, 8]
                  const float* __restrict__ rp,    // [8]
                  float* __restrict__ out,         // [ntok, 128]
                  int ntok)
{
    __shared__ float e_buf[NWARPS][STAGES][DIM];   // 32 KB
    __shared__ float b_buf[NWARPS][STAGES][RANK];  // 2 KB

    const int lane = threadIdx.x & 31;
    const int w    = threadIdx.x >> 5;
    const int warp_global = blockIdx.x * NWARPS + w;

    // ---- inline index-dtype detection ----
    const long long* x64 = reinterpret_cast<const long long*>(xv);
    const int*       x32 = reinterpret_cast<const int*>(xv);
    long long probe = x64[lane];
    bool bad = (probe < 0) || (probe >= (long long)VOCAB);
    const bool is64 = (__ballot_sync(0xFFFFFFFFu, bad) == 0u);

    const uint64_t pol = mk_evict_last_policy();

    // Gated+scaled A columns for this lane's 4 dims, packed as f32x2 pairs.
    uint64_t a2[RANK][2];
#pragma unroll
    for (int r = 0; r < RANK; r++) {
        float g = (rp[r] > RANK_THRESHOLD) ? SCALING : 0.0f;
        float4 av = reinterpret_cast<const float4*>(A)[r * (DIM / 4) + lane];
        a2[r][0] = pack2(av.x * g, av.y * g);
        a2[r][1] = pack2(av.z * g, av.w * g);
    }

    const int base = warp_global * CHUNK;
    if (base >= ntok) return;
    const int tend = min(base + CHUNK, ntok);
    const int nt = tend - base;

    const uint32_t e_base = (uint32_t)__cvta_generic_to_shared(&e_buf[w][0][0]);
    const uint32_t b_base = (uint32_t)__cvta_generic_to_shared(&b_buf[w][0][0]);

    // ---------------- prologue: fill pipeline ----------------
#pragma unroll
    for (int s = 0; s < STAGES; s++) {
        int t = base + s;
        if (t < tend) {
            uint32_t idx = is64 ? (uint32_t)x64[t] : (uint32_t)x32[t];
            cp_async16_el(e_base + (uint32_t)(s * DIM + lane * 4) * 4,
                          E + (size_t)idx * DIM + lane * 4, pol);
            if (lane < 2)
                cp_async16_el(b_base + (uint32_t)(s * RANK + lane * 4) * 4,
                              Bm + (size_t)idx * RANK + lane * 4, pol);
        }
        cp_commit();
    }

    // ---------------- steady state ----------------
    for (int i = 0; i < nt; i++) {
        asm volatile("cp.async.wait_group %0;\n" :: "n"(STAGES - 1));
        __syncwarp();   // make lanes 0/1's B copies visible to all lanes

        const int s = i & (STAGES - 1);
        float4 e  = *reinterpret_cast<const float4*>(&e_buf[w][s][lane * 4]);
        float4 b0 = *reinterpret_cast<const float4*>(&b_buf[w][s][0]);
        float4 b1 = *reinterpret_cast<const float4*>(&b_buf[w][s][4]);

        __syncwarp();   // all lanes done reading stage s before refill

        int t = base + i + STAGES;
        if (t < tend) {
            uint32_t idx = is64 ? (uint32_t)x64[t] : (uint32_t)x32[t];
            cp_async16_el(e_base + (uint32_t)(s * DIM + lane * 4) * 4,
                          E + (size_t)idx * DIM + lane * 4, pol);
            if (lane < 2)
                cp_async16_el(b_base + (uint32_t)(s * RANK + lane * 4) * 4,
                              Bm + (size_t)idx * RANK + lane * 4, pol);
        }
        cp_commit();

        // packed f32x2 math: 16 FFMA2 + 8 broadcasts instead of 32 FFMA
        uint64_t o0 = pack2(e.x, e.y);
        uint64_t o1 = pack2(e.z, e.w);
        uint64_t bb;
        bb = bcast2(b0.x); o0 = fma2(bb, a2[0][0], o0); o1 = fma2(bb, a2[0][1], o1);
        bb = bcast2(b0.y); o0 = fma2(bb, a2[1][0], o0); o1 = fma2(bb, a2[1][1], o1);
        bb = bcast2(b0.z); o0 = fma2(bb, a2[2][0], o0); o1 = fma2(bb, a2[2][1], o1);
        bb = bcast2(b0.w); o0 = fma2(bb, a2[3][0], o0); o1 = fma2(bb, a2[3][1], o1);
        bb = bcast2(b1.x); o0 = fma2(bb, a2[4][0], o0); o1 = fma2(bb, a2[4][1], o1);
        bb = bcast2(b1.y); o0 = fma2(bb, a2[5][0], o0); o1 = fma2(bb, a2[5][1], o1);
        bb = bcast2(b1.z); o0 = fma2(bb, a2[6][0], o0); o1 = fma2(bb, a2[6][1], o1);
        bb = bcast2(b1.w); o0 = fma2(bb, a2[7][0], o0); o1 = fma2(bb, a2[7][1], o1);

        float4 o;
        unpack2(o0, o.x, o.y);
        unpack2(o1, o.z, o.w);

        __stcs(reinterpret_cast<float4*>(out + (size_t)(base + i) * DIM) + lane, o);
    }
}

extern "C" void kernel_launch(void* const* d_in, const int* in_sizes, int n_in,
                              void* d_out, int out_size)
{
    const void*  x  = d_in[0];                // [B, L] int32 or int64
    const float* E  = (const float*)d_in[1];  // [VOCAB, 128]
    const float* A  = (const float*)d_in[2];  // [8, 128]
    const float* Bm = (const float*)d_in[3];  // [VOCAB, 8]
    const float* rp = (const float*)d_in[4];  // [8]
    float* out = (float*)d_out;

    const int ntok = out_size / DIM;

    const int tok_per_block = NWARPS * CHUNK;                // 512
    int blocks = (ntok + tok_per_block - 1) / tok_per_block; // 1600
    cora_embed_kernel<<<blocks, NWARPS * 32>>>(x, E, A, Bm, rp, out, ntok);
}